// round 13
// baseline (speedup 1.0000x reference)
#include <cuda_runtime.h>

// NeuS render: pixel/invdepth/weight from sdf+color+z_vals.
// Telescoping identity: trans[i] = sig[i]/sig[0], so
//   weight[i] = max(sig[i]-sig[i+1], 0) / sig[0], weight[0]=weight[S-1]=0.
// Background fold: pixel = bg + sum_i w[i]*(c[i]-bg).
// TWO rays per warp, 4 samples per lane per ray: all 10 LDG.128 front-batched
// (doubles per-warp MLP), one fused 8-value butterfly reduction (halves
// shuffle cost per ray). Evict-first loads; write-through weight stores.
// Output layout: pixel[R*3] | invdepth[R] | weight[R*S].

#define N_RAYS    65536
#define N_SAMPLES 128

__global__ __launch_bounds__(256)
void neus_render_kernel(const float* __restrict__ sdf,
                        const float* __restrict__ color,
                        const float* __restrict__ z_vals,
                        const float* __restrict__ s_ptr,
                        const float* __restrict__ bg,
                        float* __restrict__ out)
{
    const int warp_id = (blockIdx.x * blockDim.x + threadIdx.x) >> 5;
    const int lane    = threadIdx.x & 31;

    const float s   = __ldg(s_ptr);
    const float bgr = __ldg(bg + 0);
    const float bgg = __ldg(bg + 1);
    const float bgb = __ldg(bg + 2);

    const size_t ray0 = (size_t)warp_id * 2;
    const size_t ray1 = ray0 + 1;

    const float4* sdf0 = (const float4*)(sdf + ray0 * N_SAMPLES) + lane;
    const float4* z0   = (const float4*)(z_vals + ray0 * N_SAMPLES) + lane;
    const float4* c0p  = (const float4*)(color + ray0 * (size_t)(N_SAMPLES * 3)) + lane * 3;
    const float4* sdf1 = (const float4*)(sdf + ray1 * N_SAMPLES) + lane;
    const float4* z1   = (const float4*)(z_vals + ray1 * N_SAMPLES) + lane;
    const float4* c1p  = (const float4*)(color + ray1 * (size_t)(N_SAMPLES * 3)) + lane * 3;

    // ---- 10 streaming loads, front-batched (MLP_p1 = 10) ----
    const float4 sdA = __ldcs(sdf0);
    const float4 sdB = __ldcs(sdf1);
    const float4 zzA = __ldcs(z0);
    const float4 zzB = __ldcs(z1);
    const float4 a0 = __ldcs(c0p + 0);
    const float4 a1 = __ldcs(c0p + 1);
    const float4 a2 = __ldcs(c0p + 2);
    const float4 b0 = __ldcs(c1p + 0);
    const float4 b1 = __ldcs(c1p + 1);
    const float4 b2 = __ldcs(c1p + 2);

    // ---- ray 0 sigmoids / weights ----
    const float s0A = 1.0f / (1.0f + __expf(-sdA.x * s));
    const float s0B = 1.0f / (1.0f + __expf(-sdA.y * s));
    const float s0C = 1.0f / (1.0f + __expf(-sdA.z * s));
    const float s0D = 1.0f / (1.0f + __expf(-sdA.w * s));
    const float s1A = 1.0f / (1.0f + __expf(-sdB.x * s));
    const float s1B = 1.0f / (1.0f + __expf(-sdB.y * s));
    const float s1C = 1.0f / (1.0f + __expf(-sdB.z * s));
    const float s1D = 1.0f / (1.0f + __expf(-sdB.w * s));

    const float s0Next = __shfl_down_sync(0xffffffffu, s0A, 1);
    const float s1Next = __shfl_down_sync(0xffffffffu, s1A, 1);
    const float inv00  = 1.0f / __shfl_sync(0xffffffffu, s0A, 0);
    const float inv10  = 1.0f / __shfl_sync(0xffffffffu, s1A, 0);

    float4 w0, w1;
    w0.x = (lane == 0)  ? 0.0f : fmaxf(s0A - s0B, 0.0f) * inv00;
    w0.y =                       fmaxf(s0B - s0C, 0.0f) * inv00;
    w0.z =                       fmaxf(s0C - s0D, 0.0f) * inv00;
    w0.w = (lane == 31) ? 0.0f : fmaxf(s0D - s0Next, 0.0f) * inv00;
    w1.x = (lane == 0)  ? 0.0f : fmaxf(s1A - s1B, 0.0f) * inv10;
    w1.y =                       fmaxf(s1B - s1C, 0.0f) * inv10;
    w1.z =                       fmaxf(s1C - s1D, 0.0f) * inv10;
    w1.w = (lane == 31) ? 0.0f : fmaxf(s1D - s1Next, 0.0f) * inv10;

    // ---- write-through weight stores, issued early ----
    float* wbase = out + (size_t)N_RAYS * 4;
    __stwt((float4*)(wbase + ray0 * N_SAMPLES) + lane, w0);
    __stwt((float4*)(wbase + ray1 * N_SAMPLES) + lane, w1);

    // ---- per-lane partials ----
    float invd0 = __fdividef(w0.x, zzA.x) + __fdividef(w0.y, zzA.y)
                + __fdividef(w0.z, zzA.z) + __fdividef(w0.w, zzA.w);
    float invd1 = __fdividef(w1.x, zzB.x) + __fdividef(w1.y, zzB.y)
                + __fdividef(w1.z, zzB.z) + __fdividef(w1.w, zzB.w);

    // pixel = bg + sum w*(c - bg)
    float pr0 = w0.x*(a0.x-bgr) + w0.y*(a0.w-bgr) + w0.z*(a1.z-bgr) + w0.w*(a2.y-bgr);
    float pg0 = w0.x*(a0.y-bgg) + w0.y*(a1.x-bgg) + w0.z*(a1.w-bgg) + w0.w*(a2.z-bgg);
    float pb0 = w0.x*(a0.z-bgb) + w0.y*(a1.y-bgb) + w0.z*(a2.x-bgb) + w0.w*(a2.w-bgb);
    float pr1 = w1.x*(b0.x-bgr) + w1.y*(b0.w-bgr) + w1.z*(b1.z-bgr) + w1.w*(b2.y-bgr);
    float pg1 = w1.x*(b0.y-bgg) + w1.y*(b1.x-bgg) + w1.z*(b1.w-bgg) + w1.w*(b2.z-bgg);
    float pb1 = w1.x*(b0.z-bgb) + w1.y*(b1.y-bgb) + w1.z*(b2.x-bgb) + w1.w*(b2.w-bgb);

    // ---- fused 8-value butterfly reduction (5 rounds) ----
    #pragma unroll
    for (int off = 16; off > 0; off >>= 1) {
        pr0   += __shfl_xor_sync(0xffffffffu, pr0,   off);
        pg0   += __shfl_xor_sync(0xffffffffu, pg0,   off);
        pb0   += __shfl_xor_sync(0xffffffffu, pb0,   off);
        invd0 += __shfl_xor_sync(0xffffffffu, invd0, off);
        pr1   += __shfl_xor_sync(0xffffffffu, pr1,   off);
        pg1   += __shfl_xor_sync(0xffffffffu, pg1,   off);
        pb1   += __shfl_xor_sync(0xffffffffu, pb1,   off);
        invd1 += __shfl_xor_sync(0xffffffffu, invd1, off);
    }

    if (lane == 0) {
        out[ray0 * 3 + 0] = pr0 + bgr;
        out[ray0 * 3 + 1] = pg0 + bgg;
        out[ray0 * 3 + 2] = pb0 + bgb;
        out[ray1 * 3 + 0] = pr1 + bgr;
        out[ray1 * 3 + 1] = pg1 + bgg;
        out[ray1 * 3 + 2] = pb1 + bgb;
        out[(size_t)N_RAYS * 3 + ray0] = invd0;
        out[(size_t)N_RAYS * 3 + ray1] = invd1;
    }
}

extern "C" void kernel_launch(void* const* d_in, const int* in_sizes, int n_in,
                              void* d_out, int out_size)
{
    const float* sdf    = (const float*)d_in[0];
    const float* color  = (const float*)d_in[1];
    const float* z_vals = (const float*)d_in[2];
    const float* s      = (const float*)d_in[3];
    const float* bg     = (const float*)d_in[4];
    float* out = (float*)d_out;

    // 256 threads = 8 warps = 16 rays per block (2 rays/warp)
    const int block = 256;
    const int grid  = N_RAYS / 16;
    neus_render_kernel<<<grid, block>>>(sdf, color, z_vals, s, bg, out);
}